// round 16
// baseline (speedup 1.0000x reference)
#include <cuda_runtime.h>
#include <cuda_bf16.h>
#include <math.h>
#include <stdint.h>

// Problem constants
#define LAYERS 4
#define D_     128
#define N_     2048
#define TWON   4096
#define INV_T  5.0f
#define EPS    1e-12f
#define C_EX2  7.21347520444481703076f   // (1/T) * log2(e)
#define SQC    2.68579079f               // sqrt(C_EX2); z stored as z*SQC => acc = C_EX2*s
#define LN2F   0.69314718056f            // INV_T / C_EX2

#define SROWB  272                       // smem row stride bytes (128 bf16 + 16B pad)
#define TILEB  (128 * SROWB)             // 34816
#define NTILE  32                        // 4096/128 blocks per layer
#define TOPSL  528                       // NTILE*(NTILE+1)/2 tile-ops per layer
#define TOTOPS (LAYERS * TOPSL)          // 2112
#define NCTA   296                       // 2 CTAs per SM
#define RUNLEN 7                         // static contiguous ops per CTA (296*7=2072)
#define TAIL0  (NCTA * RUNLEN)           // 2072; tail ops 2072..2111 are stolen
#define RBLK   64                        // reduction blocks (16384 rows / 256)

// Scratch
__device__ __align__(256) __nv_bfloat16 g_zb[LAYERS * TWON * D_];
__device__ float g_acc[LAYERS * NTILE * NTILE * 128];  // [l][i][j][rl] exp-sums (2MB)
__device__ float g_diag[LAYERS * TWON];                // scaled diag acc (C*s_ii)
__device__ float g_posv[LAYERS * N_];                  // scaled pos acc (C*s_pos)
__device__ float g_part[RBLK];                         // per-block masked partials
__device__ unsigned int g_ctr;                         // last-block counter (self-resetting)
__device__ unsigned int g_tick;                        // tail ticket (reset by lp_reduce)

// ---------------------------------------------------------------------------
__device__ __forceinline__ uint32_t smem_u32(const void* p) {
    uint32_t a;
    asm("{ .reg .u64 t; cvta.to.shared.u64 t, %1; cvt.u32.u64 %0, t; }" : "=r"(a) : "l"(p));
    return a;
}
__device__ __forceinline__ float ex2f(float x) {
    float r; asm("ex2.approx.ftz.f32 %0, %1;" : "=f"(r) : "f"(x)); return r;
}
#define CP_ASYNC16(dst, src) \
    asm volatile("cp.async.cg.shared.global [%0], [%1], 16;" :: "r"(dst), "l"(src))
#define CP_COMMIT() asm volatile("cp.async.commit_group;" ::: "memory")
#define CP_WAIT(n)  asm volatile("cp.async.wait_group %0;" :: "n"(n) : "memory")

__device__ __forceinline__ void ldsm4(uint32_t* r, uint32_t addr) {
    asm volatile("ldmatrix.sync.aligned.m8n8.x4.shared.b16 {%0,%1,%2,%3}, [%4];"
                 : "=r"(r[0]), "=r"(r[1]), "=r"(r[2]), "=r"(r[3]) : "r"(addr));
}
__device__ __forceinline__ void mma_bf16(float* c, const uint32_t* a, const uint32_t* b) {
    asm volatile(
        "mma.sync.aligned.m16n8k16.row.col.f32.bf16.bf16.f32 "
        "{%0,%1,%2,%3}, {%4,%5,%6,%7}, {%8,%9}, {%0,%1,%2,%3};"
        : "+f"(c[0]), "+f"(c[1]), "+f"(c[2]), "+f"(c[3])
        : "r"(a[0]), "r"(a[1]), "r"(a[2]), "r"(a[3]), "r"(b[0]), "r"(b[1]));
}

// ---------------------------------------------------------------------------
// Kernel 1: L2-normalize -> bf16 (pre-scaled by sqrt(C_EX2)).
// Persistent: 256 CTAs; each warp owns 8 consecutive rows, 2-way unrolled
// (two independent LDG+shuffle chains in flight).
// ---------------------------------------------------------------------------
__device__ __forceinline__ void norm_row(const float* __restrict__ emb_i,
                                         const float* __restrict__ emb_j,
                                         int gr, int lane) {
    int layer = gr >> 12;
    int row   = gr & (TWON - 1);
    const float* src = (row < N_)
        ? (emb_i + ((size_t)layer * N_ + row) * D_)
        : (emb_j + ((size_t)layer * N_ + (row - N_)) * D_);

    float4 v = ((const float4*)src)[lane];
    float s = v.x * v.x + v.y * v.y + v.z * v.z + v.w * v.w;
    #pragma unroll
    for (int o = 16; o > 0; o >>= 1) s += __shfl_xor_sync(0xffffffffu, s, o);

    float inv = SQC * rsqrtf(fmaxf(s, EPS * EPS));
    uint2 u;
    u.x = (uint32_t)__bfloat16_as_ushort(__float2bfloat16(v.x * inv))
        | ((uint32_t)__bfloat16_as_ushort(__float2bfloat16(v.y * inv)) << 16);
    u.y = (uint32_t)__bfloat16_as_ushort(__float2bfloat16(v.z * inv))
        | ((uint32_t)__bfloat16_as_ushort(__float2bfloat16(v.w * inv)) << 16);
    ((uint2*)(g_zb + (size_t)gr * D_))[lane] = u;
}

__global__ void __launch_bounds__(256) norm_bf16_kernel(const float* __restrict__ emb_i,
                                                        const float* __restrict__ emb_j) {
    int gw   = (blockIdx.x * blockDim.x + threadIdx.x) >> 5;   // 2048 warps
    int lane = threadIdx.x & 31;
    int base = gw * 8;                                         // 8 rows per warp

    #pragma unroll 1
    for (int k = 0; k < 8; k += 2) {
        norm_row(emb_i, emb_j, base + k,     lane);
        norm_row(emb_i, emb_j, base + k + 1, lane);
    }
}

// ---------------------------------------------------------------------------
// Kernel 2: symmetric fused Gram + exp.  296 CTAs x 256 threads, 2 CTAs/SM.
// Static contiguous 7-op runs (A-block resident, B double-buffered+prefetched)
// plus a 40-op stolen tail for load balance.  (Unchanged from R15.)
// ---------------------------------------------------------------------------
extern __shared__ char dsm[];

__device__ __forceinline__ void unrank(int t, int& layer, int& ib, int& jb) {
    layer = t / TOPSL;
    int rem = t - layer * TOPSL;
    int i = 0;
    while (rem >= NTILE - i) { rem -= NTILE - i; ++i; }
    ib = i; jb = i + rem;
}

__device__ __forceinline__ void load_tile(int layer, int blk, uint32_t base, int tid) {
    const __nv_bfloat16* P = g_zb + (size_t)layer * TWON * D_ + (size_t)blk * 128 * D_;
    #pragma unroll
    for (int p = 0; p < 8; ++p) {
        int idx = p * 256 + tid;               // 2048 16B segs
        int r = idx >> 4, sc = idx & 15;
        CP_ASYNC16(base + r * SROWB + sc * 16,
                   (const char*)(P + (size_t)r * D_) + sc * 16);
    }
}

struct OpCtx {
    int layer, ib, jb;
};

__device__ __forceinline__ void do_op(const OpCtx& op, uint32_t bufA, uint32_t bufB,
                                      int tid, int lane, int warpRow, int warpCol,
                                      uint32_t laneA, uint32_t laneB,
                                      float (*red_r)[128], float (*red_c)[128]) {
    uint32_t aA = bufA + (uint32_t)(warpRow * 32 * SROWB) + laneA;
    uint32_t bA = bufB + (uint32_t)(warpCol * 64 * SROWB) + laneB;

    float acc[2][8][4];
    #pragma unroll
    for (int mt = 0; mt < 2; ++mt)
        #pragma unroll
        for (int nt = 0; nt < 8; ++nt)
            #pragma unroll
            for (int ci = 0; ci < 4; ++ci) acc[mt][nt][ci] = 0.f;

    #pragma unroll
    for (int kt = 0; kt < 8; ++kt) {
        uint32_t aF0[4], aF1[4];
        ldsm4(aF0, aA + (uint32_t)(kt * 32));
        ldsm4(aF1, aA + (uint32_t)(16 * SROWB + kt * 32));
        #pragma unroll
        for (int np = 0; np < 4; ++np) {
            uint32_t tt[4];
            ldsm4(tt, bA + (uint32_t)(np * 16 * SROWB + kt * 32));
            mma_bf16(acc[0][2 * np],     aF0, &tt[0]);
            mma_bf16(acc[0][2 * np + 1], aF0, &tt[2]);
            mma_bf16(acc[1][2 * np],     aF1, &tt[0]);
            mma_bf16(acc[1][2 * np + 1], aF1, &tt[2]);
        }
    }

    bool isDiag = (op.ib == op.jb);
    bool isPos  = (op.jb == op.ib + (N_ / 128));

    float dsum[4] = {0.f, 0.f, 0.f, 0.f};
    float csum[16];
    #pragma unroll
    for (int x = 0; x < 16; ++x) csum[x] = 0.f;

    #pragma unroll
    for (int mt = 0; mt < 2; ++mt)
        #pragma unroll
        for (int nt = 0; nt < 8; ++nt)
            #pragma unroll
            for (int ci = 0; ci < 4; ++ci) {
                float s = acc[mt][nt][ci];       // already C_EX2-scaled
                float e = ex2f(s);
                dsum[mt * 2 + (ci >> 1)] += e;
                csum[nt * 2 + (ci & 1)] += e;
                if (isDiag | isPos) {
                    int rl = warpRow * 32 + (lane >> 2) + mt * 16 + (ci >> 1) * 8;
                    int cl = warpCol * 64 + nt * 8 + (lane & 3) * 2 + (ci & 1);
                    if (rl == cl) {
                        if (isDiag) g_diag[op.layer * TWON + op.ib * 128 + rl] = s;
                        else        g_posv[op.layer * N_   + op.ib * 128 + rl] = s;
                    }
                }
            }

    #pragma unroll
    for (int ri = 0; ri < 4; ++ri) {
        #pragma unroll
        for (int o = 1; o <= 2; o <<= 1)
            dsum[ri] += __shfl_xor_sync(0xffffffffu, dsum[ri], o);
    }
    if ((lane & 3) == 0) {
        #pragma unroll
        for (int ri = 0; ri < 4; ++ri) {
            int rloc = warpRow * 32 + (ri >> 1) * 16 + (ri & 1) * 8 + (lane >> 2);
            red_r[warpCol][rloc] = dsum[ri];
        }
    }
    #pragma unroll
    for (int x = 0; x < 16; ++x) {
        #pragma unroll
        for (int o = 4; o <= 16; o <<= 1)
            csum[x] += __shfl_xor_sync(0xffffffffu, csum[x], o);
    }
    if (lane < 4) {
        #pragma unroll
        for (int x = 0; x < 16; ++x) {
            int cl = warpCol * 64 + (x >> 1) * 8 + lane * 2 + (x & 1);
            red_c[warpRow][cl] = csum[x];
        }
    }
    __syncthreads();            // red complete; all smem tile reads complete

    if (tid < 128) {
        float rs = red_r[0][tid] + red_r[1][tid];
        g_acc[(((size_t)op.layer * NTILE + op.ib) * NTILE + op.jb) * 128 + tid] = rs;
    } else if (!isDiag) {
        int c = tid - 128;
        float cs = red_c[0][c] + red_c[1][c] + red_c[2][c] + red_c[3][c];
        g_acc[(((size_t)op.layer * NTILE + op.jb) * NTILE + op.ib) * 128 + c] = cs;
    }
}

__global__ void __launch_bounds__(256, 2) sim_sym_kernel() {
    __shared__ float red_r[2][128];
    __shared__ float red_c[4][128];

    int tid  = threadIdx.x;
    int wid  = tid >> 5;
    int lane = tid & 31;
    int warpRow = wid & 3;      // 4 slices of 32 rows
    int warpCol = wid >> 2;     // 2 slices of 64 cols

    uint32_t sb = (smem_u32(dsm) + 1023) & ~1023u;
    uint32_t bufA = sb;
    uint32_t bufB[2] = { sb + TILEB, sb + 2 * TILEB };

    uint32_t laneA = (uint32_t)((lane & 7) * SROWB + ((lane >> 3) & 1) * (8 * SROWB)
                                + ((lane >> 4) & 1) * 16);
    uint32_t laneB = (uint32_t)((lane & 7) * SROWB + ((lane >> 3) & 1) * 16
                                + ((lane >> 4) & 1) * (8 * SROWB));

    // ---- static run: ops [c*7, c*7+7) ----
    int start = (int)blockIdx.x * RUNLEN;
    OpCtx cur, nxt;
    unrank(start, cur.layer, cur.ib, cur.jb);

    load_tile(cur.layer, cur.ib, bufA, tid);
    load_tile(cur.layer, cur.jb, bufB[0], tid);
    CP_COMMIT();

    int p = 0;
    #pragma unroll 1
    for (int k = 0; k < RUNLEN; ++k) {
        int tcur = start + k;
        int haveNext = (k + 1 < RUNLEN);
        if (haveNext) unrank(tcur + 1, nxt.layer, nxt.ib, nxt.jb);

        CP_WAIT(0);
        bool crossing = haveNext && (nxt.ib != cur.ib || nxt.layer != cur.layer);
        __syncthreads();        // bufA/bufB[p] ready; red free; prior flush done

        if (haveNext) {
            load_tile(nxt.layer, nxt.jb, bufB[p ^ 1], tid);
            CP_COMMIT();
        }

        do_op(cur, bufA, bufB[p], tid, lane, warpRow, warpCol, laneA, laneB,
              red_r, red_c);

        if (haveNext) {
            if (crossing) {
                CP_WAIT(0);
                load_tile(nxt.layer, nxt.ib, bufA, tid);
                CP_COMMIT();
            }
            cur = nxt;
            p ^= 1;
        }
    }

    // ---- stolen tail: ops TAIL0..TOTOPS-1, blocking loads ----
    __shared__ int s_t;
    while (true) {
        __syncthreads();        // protects s_t reuse + red arrays + buffers
        if (tid == 0) s_t = TAIL0 + (int)atomicAdd(&g_tick, 1u);
        __syncthreads();
        int t = s_t;
        if (t >= TOTOPS) break;

        OpCtx op;
        unrank(t, op.layer, op.ib, op.jb);
        load_tile(op.layer, op.ib, bufA, tid);
        load_tile(op.layer, op.jb, bufB[0], tid);
        CP_COMMIT();
        CP_WAIT(0);
        __syncthreads();

        do_op(op, bufA, bufB[0], tid, lane, warpRow, warpCol, laneA, laneB,
              red_r, red_c);
    }
}

// ---------------------------------------------------------------------------
// Kernel 3: lp + mask + block partials + fused last-block final combine.
// ---------------------------------------------------------------------------
__global__ void lp_reduce_kernel(const float* __restrict__ joint_valid,
                                 float* __restrict__ out) {
    __shared__ float s1[256];
    __shared__ unsigned int isLast;
    int tid  = threadIdx.x;
    int ridx = blockIdx.x * 256 + tid;     // [0, LAYERS*TWON)
    int layer = ridx >> 12;
    int r     = ridx & (TWON - 1);
    int blk   = r >> 7;
    int rl    = r & 127;

    const float* slots = g_acc + (((size_t)layer * NTILE + blk) * NTILE) * 128 + rl;
    float d = 0.f;
    #pragma unroll
    for (int k = 0; k < NTILE; ++k) d += slots[k * 128];

    float denom = d - ex2f(g_diag[ridx]);                 // remove self term
    float posac = g_posv[layer * N_ + (r & (N_ - 1))];    // C*s_pos
    float lp = logf(denom) - posac * LN2F;

    s1[tid] = lp * joint_valid[r & (N_ - 1)];
    __syncthreads();
    #pragma unroll
    for (int s = 128; s > 0; s >>= 1) {
        if (tid < s) s1[tid] += s1[tid + s];
        __syncthreads();
    }
    if (tid == 0) {
        g_part[blockIdx.x] = s1[0];
        __threadfence();
        unsigned int prev = atomicAdd(&g_ctr, 1u);
        isLast = (prev == RBLK - 1) ? 1u : 0u;
    }
    __syncthreads();

    if (isLast) {
        __threadfence();                  // see all g_part writes
        float tpart = (tid < RBLK) ? g_part[tid] : 0.f;
        float an = 0.f;
        #pragma unroll
        for (int k = 0; k < N_ / 256; ++k) an += joint_valid[k * 256 + tid];

        __shared__ float s2[256];
        s1[tid] = tpart;
        s2[tid] = an;
        __syncthreads();
        #pragma unroll
        for (int s = 128; s > 0; s >>= 1) {
            if (tid < s) { s1[tid] += s1[tid + s]; s2[tid] += s2[tid + s]; }
            __syncthreads();
        }
        if (tid == 0) {
            out[0] = s1[0] / (2.0f * s2[0]);
            g_ctr  = 0u;                  // reset for next graph replay
            g_tick = 0u;                  // reset tail ticket
        }
    }
}

// ---------------------------------------------------------------------------
extern "C" void kernel_launch(void* const* d_in, const int* in_sizes, int n_in,
                              void* d_out, int out_size) {
    const float* emb_i       = (const float*)d_in[0];
    const float* emb_j       = (const float*)d_in[1];
    const float* joint_valid = (const float*)d_in[2];
    float* out = (float*)d_out;
    (void)in_sizes; (void)n_in; (void)out_size;

    const int SIM_SMEM = 1024 + 3 * TILEB;   // A + 2xB = 105472 B per CTA
    cudaFuncSetAttribute(sim_sym_kernel, cudaFuncAttributeMaxDynamicSharedMemorySize, SIM_SMEM);

    norm_bf16_kernel<<<256, 256>>>(emb_i, emb_j);   // 2048 warps x 8 rows
    sim_sym_kernel<<<NCTA, 256, SIM_SMEM>>>();
    lp_reduce_kernel<<<RBLK, 256>>>(joint_valid, out);
}